// round 1
// baseline (speedup 1.0000x reference)
#include <cuda_runtime.h>
#include <math.h>

#define BB 2
#define TT 2048
#define CC 1024
#define NH 16
#define HD 64
#define BH (BB*NH)

// Scratch: q,k,v,att in (B,H,T,hd) layout. 4 x 16MB fp32.
__device__ float g_q[(size_t)BH * TT * HD];
__device__ float g_k[(size_t)BH * TT * HD];
__device__ float g_v[(size_t)BH * TT * HD];
__device__ float g_att[(size_t)BH * TT * HD];

// ---------------------------------------------------------------------------
// Kernel 1: QKV GEMM.  x(4096,1024) @ Wqkv(1024,3072) + bqkv,
// scatter columns n = h*192 + r into q/k/v (B,H,T,hd).
// 64x64 tile, BK=16, 256 threads, 4x4 micro-tile.
// ---------------------------------------------------------------------------
__global__ __launch_bounds__(256) void qkv_gemm_kernel(
    const float* __restrict__ x, const float* __restrict__ W,
    const float* __restrict__ bias)
{
    __shared__ float As[16][68];   // A^T tile: [k][m], padded row
    __shared__ float Bs[16][64];   // B tile: [k][n]

    const int tid = threadIdx.x;
    const int tx = tid & 15, ty = tid >> 4;
    const int m0 = blockIdx.y << 6, n0 = blockIdx.x << 6;

    const int ar = tid >> 2;          // 0..63 row of A tile
    const int ac = (tid & 3) << 2;    // 0,4,8,12 col of A tile
    const int br = tid >> 4;          // 0..15 row of B tile
    const int bc = (tid & 15) << 2;   // 0..60 col of B tile

    float acc[4][4] = {};

    for (int k0 = 0; k0 < CC; k0 += 16) {
        float4 av = *(const float4*)&x[(size_t)(m0 + ar) * CC + k0 + ac];
        float4 bv = *(const float4*)&W[(size_t)(k0 + br) * (3 * CC) + n0 + bc];
        As[ac + 0][ar] = av.x;
        As[ac + 1][ar] = av.y;
        As[ac + 2][ar] = av.z;
        As[ac + 3][ar] = av.w;
        *(float4*)&Bs[br][bc] = bv;
        __syncthreads();

        #pragma unroll
        for (int kk = 0; kk < 16; kk++) {
            float4 a = *(const float4*)&As[kk][ty << 2];
            float4 b = *(const float4*)&Bs[kk][tx << 2];
            acc[0][0] += a.x * b.x; acc[0][1] += a.x * b.y; acc[0][2] += a.x * b.z; acc[0][3] += a.x * b.w;
            acc[1][0] += a.y * b.x; acc[1][1] += a.y * b.y; acc[1][2] += a.y * b.z; acc[1][3] += a.y * b.w;
            acc[2][0] += a.z * b.x; acc[2][1] += a.z * b.y; acc[2][2] += a.z * b.z; acc[2][3] += a.z * b.w;
            acc[3][0] += a.w * b.x; acc[3][1] += a.w * b.y; acc[3][2] += a.w * b.z; acc[3][3] += a.w * b.w;
        }
        __syncthreads();
    }

    #pragma unroll
    for (int i = 0; i < 4; i++) {
        int m = m0 + (ty << 2) + i;
        int b = m >> 11, t = m & 2047;
        #pragma unroll
        for (int j = 0; j < 4; j++) {
            int n = n0 + (tx << 2) + j;
            float v = acc[i][j] + bias[n];
            int h = n / 192;
            int r = n - h * 192;        // 0..191 within head
            int d = r & 63;
            float* dst = (r < 64) ? g_q : (r < 128) ? g_k : g_v;
            dst[((size_t)(((b << 4) + h) << 11) + t) * HD + d] = v;
        }
    }
}

// ---------------------------------------------------------------------------
// Kernel 2: causal flash attention, fp32, online softmax.
// One block per (bh, 64-query tile). 256 threads: 4 threads per query row.
// Each thread: 16 score cols (kj = lane + 4*ii), 16 output dims (lane*16..).
// ---------------------------------------------------------------------------
#define PAD 68

__global__ __launch_bounds__(256) void attn_kernel()
{
    extern __shared__ float sm[];
    float* sQ = sm;
    float* sK = sm + 64 * PAD;
    float* sV = sm + 2 * 64 * PAD;
    float* sP = sm + 3 * 64 * PAD;

    const int qt = blockIdx.x;
    const int bh = blockIdx.y;
    const int tid = threadIdx.x;
    const int qi = tid >> 2;
    const int lane = tid & 3;

    const float* Qg = g_q + (size_t)bh * TT * HD + (size_t)qt * 64 * HD;
    const float* Kg = g_k + (size_t)bh * TT * HD;
    const float* Vg = g_v + (size_t)bh * TT * HD;

    #pragma unroll
    for (int i = 0; i < 16; i++) {
        int lin = (i << 8) + tid;
        int r = lin >> 6, c = lin & 63;
        sQ[r * PAD + c] = Qg[(r << 6) + c];
    }

    float mrow = -1e30f, lrow = 0.f;
    float acc[16];
    #pragma unroll
    for (int j = 0; j < 16; j++) acc[j] = 0.f;

    for (int kt = 0; kt <= qt; kt++) {
        __syncthreads();   // protects sK/sV overwrite & first-tile sQ visibility
        #pragma unroll
        for (int i = 0; i < 16; i++) {
            int lin = (i << 8) + tid;
            int r = lin >> 6, c = lin & 63;
            sK[r * PAD + c] = Kg[(size_t)((kt << 6) + r) * HD + c];
            sV[r * PAD + c] = Vg[(size_t)((kt << 6) + r) * HD + c];
        }
        __syncthreads();

        // ---- scores: 16 kj per thread, dot over 64 dims (float4 LDS) ----
        float s[16];
        const float* qrow = sQ + qi * PAD;
        #pragma unroll
        for (int ii = 0; ii < 16; ii++) {
            int kj = lane + (ii << 2);
            const float* krow = sK + kj * PAD;
            float dot = 0.f;
            #pragma unroll
            for (int d4 = 0; d4 < 16; d4++) {
                float4 qv = *(const float4*)&qrow[d4 << 2];
                float4 kv = *(const float4*)&krow[d4 << 2];
                dot += qv.x * kv.x + qv.y * kv.y + qv.z * kv.z + qv.w * kv.w;
            }
            dot *= 0.125f;   // 1/sqrt(64)
            if (kt == qt && kj > qi) dot = -1e30f;   // causal mask (diag tile)
            s[ii] = dot;
        }

        // ---- online softmax (4 threads per row share via shfl) ----
        float tmax = s[0];
        #pragma unroll
        for (int ii = 1; ii < 16; ii++) tmax = fmaxf(tmax, s[ii]);
        tmax = fmaxf(tmax, __shfl_xor_sync(0xffffffffu, tmax, 1));
        tmax = fmaxf(tmax, __shfl_xor_sync(0xffffffffu, tmax, 2));
        float mnew = fmaxf(mrow, tmax);
        float corr = __expf(mrow - mnew);
        float lsum = 0.f;
        #pragma unroll
        for (int ii = 0; ii < 16; ii++) {
            float p = __expf(s[ii] - mnew);
            lsum += p;
            sP[qi * PAD + lane + (ii << 2)] = p;
        }
        lsum += __shfl_xor_sync(0xffffffffu, lsum, 1);
        lsum += __shfl_xor_sync(0xffffffffu, lsum, 2);
        lrow = lrow * corr + lsum;
        mrow = mnew;
        #pragma unroll
        for (int j = 0; j < 16; j++) acc[j] *= corr;

        __syncwarp();  // sP row is produced & consumed within one warp

        // ---- O += P @ V : thread covers dims [lane*16, lane*16+16) ----
        for (int kj = 0; kj < 64; kj++) {
            float p = sP[qi * PAD + kj];
            const float* vrow = sV + kj * PAD + (lane << 4);
            #pragma unroll
            for (int j4 = 0; j4 < 4; j4++) {
                float4 vv = *(const float4*)&vrow[j4 << 2];
                acc[j4 * 4 + 0] += p * vv.x;
                acc[j4 * 4 + 1] += p * vv.y;
                acc[j4 * 4 + 2] += p * vv.z;
                acc[j4 * 4 + 3] += p * vv.w;
            }
        }
    }

    float inv = 1.f / lrow;
    float* Og = g_att + (size_t)bh * TT * HD + (size_t)qt * 64 * HD;
    #pragma unroll
    for (int j = 0; j < 16; j++)
        Og[(qi << 6) + (lane << 4) + j] = acc[j] * inv;
}

// ---------------------------------------------------------------------------
// Kernel 3: proj GEMM. A gathered from g_att (B,H,T,hd) -> (B*T, C),
// @ Wproj(1024,1024) + bproj -> d_out.
// ---------------------------------------------------------------------------
__global__ __launch_bounds__(256) void proj_gemm_kernel(
    const float* __restrict__ W, const float* __restrict__ bias,
    float* __restrict__ out)
{
    __shared__ float As[16][68];
    __shared__ float Bs[16][64];

    const int tid = threadIdx.x;
    const int tx = tid & 15, ty = tid >> 4;
    const int m0 = blockIdx.y << 6, n0 = blockIdx.x << 6;

    const int ar = tid >> 2;
    const int ac = (tid & 3) << 2;
    const int br = tid >> 4;
    const int bc = (tid & 15) << 2;

    const int m = m0 + ar;
    const int b = m >> 11, t = m & 2047;

    float acc[4][4] = {};

    for (int k0 = 0; k0 < CC; k0 += 16) {
        int k = k0 + ac;               // column of logical A = h*64 + d
        int h = k >> 6, d = k & 63;    // 4 consecutive k stay within one head
        float4 av = *(const float4*)&g_att[((size_t)(((b << 4) + h) << 11) + t) * HD + d];
        float4 bv = *(const float4*)&W[(size_t)(k0 + br) * CC + n0 + bc];
        As[ac + 0][ar] = av.x;
        As[ac + 1][ar] = av.y;
        As[ac + 2][ar] = av.z;
        As[ac + 3][ar] = av.w;
        *(float4*)&Bs[br][bc] = bv;
        __syncthreads();

        #pragma unroll
        for (int kk = 0; kk < 16; kk++) {
            float4 a = *(const float4*)&As[kk][ty << 2];
            float4 bb = *(const float4*)&Bs[kk][tx << 2];
            acc[0][0] += a.x * bb.x; acc[0][1] += a.x * bb.y; acc[0][2] += a.x * bb.z; acc[0][3] += a.x * bb.w;
            acc[1][0] += a.y * bb.x; acc[1][1] += a.y * bb.y; acc[1][2] += a.y * bb.z; acc[1][3] += a.y * bb.w;
            acc[2][0] += a.z * bb.x; acc[2][1] += a.z * bb.y; acc[2][2] += a.z * bb.z; acc[2][3] += a.z * bb.w;
            acc[3][0] += a.w * bb.x; acc[3][1] += a.w * bb.y; acc[3][2] += a.w * bb.z; acc[3][3] += a.w * bb.w;
        }
        __syncthreads();
    }

    #pragma unroll
    for (int i = 0; i < 4; i++) {
        int mm = m0 + (ty << 2) + i;
        #pragma unroll
        for (int j = 0; j < 4; j++) {
            int n = n0 + (tx << 2) + j;
            out[(size_t)mm * CC + n] = acc[i][j] + bias[n];
        }
    }
}

// ---------------------------------------------------------------------------
extern "C" void kernel_launch(void* const* d_in, const int* in_sizes, int n_in,
                              void* d_out, int out_size)
{
    const float* x     = (const float*)d_in[0];
    const float* Wqkv  = (const float*)d_in[1];
    const float* bqkv  = (const float*)d_in[2];
    const float* Wproj = (const float*)d_in[3];
    const float* bproj = (const float*)d_in[4];
    float* out = (float*)d_out;

    const size_t ATTN_SMEM = (size_t)4 * 64 * PAD * sizeof(float);  // 69632 B
    cudaFuncSetAttribute(attn_kernel,
                         cudaFuncAttributeMaxDynamicSharedMemorySize,
                         (int)ATTN_SMEM);

    // QKV: grid (N/64=48, M/64=64)
    qkv_gemm_kernel<<<dim3(48, 64), 256>>>(x, Wqkv, bqkv);
    // Attention: grid (T/64=32 query tiles, B*H=32)
    attn_kernel<<<dim3(32, 32), 256, ATTN_SMEM>>>();
    // Proj: grid (N/64=16, M/64=64)
    proj_gemm_kernel<<<dim3(16, 64), 256>>>(Wproj, bproj, out);
}

// round 2
// speedup vs baseline: 4.9421x; 4.9421x over previous
#include <cuda_runtime.h>
#include <math.h>

#define BB 2
#define TT 2048
#define CC 1024
#define NH 16
#define HD 64
#define BH (BB*NH)

__device__ float g_q[(size_t)BH * TT * HD];
__device__ float g_k[(size_t)BH * TT * HD];
__device__ float g_v[(size_t)BH * TT * HD];
__device__ float g_att[(size_t)BH * TT * HD];

// ---------------------------------------------------------------------------
// tf32 helpers
// ---------------------------------------------------------------------------
__device__ __forceinline__ unsigned f2tf(float f) {
    unsigned u;
    asm("cvt.rna.tf32.f32 %0, %1;" : "=r"(u) : "f"(f));
    return u;
}

__device__ __forceinline__ void mma8(float* c,
                                     unsigned a0, unsigned a1, unsigned a2, unsigned a3,
                                     unsigned b0, unsigned b1) {
    asm volatile(
        "mma.sync.aligned.m16n8k8.row.col.f32.tf32.tf32.f32 "
        "{%0,%1,%2,%3}, {%4,%5,%6,%7}, {%8,%9}, {%0,%1,%2,%3};"
        : "+f"(c[0]), "+f"(c[1]), "+f"(c[2]), "+f"(c[3])
        : "r"(a0), "r"(a1), "r"(a2), "r"(a3), "r"(b0), "r"(b1));
}

// ---------------------------------------------------------------------------
// Kernel 1: QKV GEMM (tf32 mma). x(4096,1024) @ Wqkv(1024,3072) + bqkv,
// scatter into q/k/v (B,H,T,hd). Block tile 128x128, BK=32, 256 threads,
// warp grid 2x4, warp tile 64x32 (4x4 m16n8k8 tiles).
// ---------------------------------------------------------------------------
__global__ __launch_bounds__(256) void qkv_mma_kernel(
    const float* __restrict__ x, const float* __restrict__ W,
    const float* __restrict__ bias)
{
    __shared__ unsigned As[128][36];  // [m][k] tf32, pad->stride%32==4
    __shared__ unsigned Bs[32][132];  // [k][n] tf32, pad->stride%32==4

    const int tid  = threadIdx.x;
    const int lane = tid & 31;
    const int warp = tid >> 5;
    const int wm = (warp >> 2) * 64;   // warp m offset in tile
    const int wn = (warp & 3) * 32;    // warp n offset in tile
    const int m0 = blockIdx.y * 128, n0 = blockIdx.x * 128;

    const int ar = tid >> 3;           // A load rows: ar, +32, +64, +96
    const int ac = (tid & 7) * 4;      // A load col4
    const int bkr = tid >> 5;          // B load k rows: bkr, +8, +16, +24
    const int bc  = (tid & 31) * 4;    // B load col4

    float C[4][4][4] = {};

    for (int k0 = 0; k0 < CC; k0 += 32) {
        float4 av[4], bv[4];
        #pragma unroll
        for (int i = 0; i < 4; i++)
            av[i] = *(const float4*)&x[(size_t)(m0 + ar + 32 * i) * CC + k0 + ac];
        #pragma unroll
        for (int i = 0; i < 4; i++)
            bv[i] = *(const float4*)&W[(size_t)(k0 + bkr + 8 * i) * (3 * CC) + n0 + bc];

        __syncthreads();
        #pragma unroll
        for (int i = 0; i < 4; i++) {
            As[ar + 32 * i][ac + 0] = f2tf(av[i].x);
            As[ar + 32 * i][ac + 1] = f2tf(av[i].y);
            As[ar + 32 * i][ac + 2] = f2tf(av[i].z);
            As[ar + 32 * i][ac + 3] = f2tf(av[i].w);
            Bs[bkr + 8 * i][bc + 0] = f2tf(bv[i].x);
            Bs[bkr + 8 * i][bc + 1] = f2tf(bv[i].y);
            Bs[bkr + 8 * i][bc + 2] = f2tf(bv[i].z);
            Bs[bkr + 8 * i][bc + 3] = f2tf(bv[i].w);
        }
        __syncthreads();

        #pragma unroll
        for (int ks = 0; ks < 4; ks++) {
            const int kc = ks * 8 + (lane & 3);
            unsigned a[4][4], b[4][2];
            #pragma unroll
            for (int tm = 0; tm < 4; tm++) {
                int r = wm + tm * 16 + (lane >> 2);
                a[tm][0] = As[r][kc];
                a[tm][1] = As[r + 8][kc];
                a[tm][2] = As[r][kc + 4];
                a[tm][3] = As[r + 8][kc + 4];
            }
            #pragma unroll
            for (int tn = 0; tn < 4; tn++) {
                int n = wn + tn * 8 + (lane >> 2);
                b[tn][0] = Bs[kc][n];
                b[tn][1] = Bs[kc + 4][n];
            }
            #pragma unroll
            for (int tm = 0; tm < 4; tm++)
                #pragma unroll
                for (int tn = 0; tn < 4; tn++)
                    mma8(C[tm][tn], a[tm][0], a[tm][1], a[tm][2], a[tm][3],
                         b[tn][0], b[tn][1]);
        }
    }

    // epilogue: bias + scatter into (B,H,T,hd) q/k/v
    #pragma unroll
    for (int tm = 0; tm < 4; tm++) {
        #pragma unroll
        for (int tn = 0; tn < 4; tn++) {
            #pragma unroll
            for (int e = 0; e < 4; e++) {
                int m = m0 + wm + tm * 16 + (lane >> 2) + ((e >= 2) ? 8 : 0);
                int n = n0 + wn + tn * 8 + 2 * (lane & 3) + (e & 1);
                float v = C[tm][tn][e] + bias[n];
                int b = m >> 11, t = m & 2047;
                int h = n / 192;
                int r = n - h * 192;
                int d = r & 63;
                float* dst = (r < 64) ? g_q : (r < 128) ? g_k : g_v;
                dst[((size_t)(((b << 4) + h) << 11) + t) * HD + d] = v;
            }
        }
    }
}

// ---------------------------------------------------------------------------
// Kernel 2: causal flash attention with tf32 mma.
// Block = 128 threads (4 warps), 64-query tile; warp w owns rows 16w..16w+15.
// S = (Q*scale) @ K^T via mma (Q frags register-resident), online softmax in
// registers, P -> smem (tf32), O += P @ V via mma.
// ---------------------------------------------------------------------------
#define APAD 68

__global__ __launch_bounds__(128) void attn_mma_kernel()
{
    extern __shared__ unsigned sm[];
    unsigned* sK = sm;                 // [64][APAD]
    unsigned* sV = sm + 64 * APAD;     // [64][APAD]
    unsigned* sP = sm + 2 * 64 * APAD; // [64][APAD]  (Q staging, then P)

    const int qt = blockIdx.x;
    const int bh = blockIdx.y;
    const int tid = threadIdx.x;
    const int lane = tid & 31;
    const int warp = tid >> 5;
    const int gi = lane >> 2;          // group row 0..7
    const int gc = lane & 3;           // group col 0..3
    const int i0 = warp * 16 + gi;     // local query row (and +8)

    const float* Qg = g_q + (size_t)bh * TT * HD + (size_t)qt * 64 * HD;
    const float* Kg = g_k + (size_t)bh * TT * HD;
    const float* Vg = g_v + (size_t)bh * TT * HD;

    // stage Q (pre-scaled) into sP, then lift fragments into registers
    #pragma unroll
    for (int i = 0; i < 8; i++) {
        int f4 = i * 128 + tid;                 // 1024 float4 total
        int r = f4 >> 4, c = (f4 & 15) << 2;
        float4 qv = *(const float4*)&Qg[(r << 6) + c];
        sP[r * APAD + c + 0] = f2tf(qv.x * 0.125f);
        sP[r * APAD + c + 1] = f2tf(qv.y * 0.125f);
        sP[r * APAD + c + 2] = f2tf(qv.z * 0.125f);
        sP[r * APAD + c + 3] = f2tf(qv.w * 0.125f);
    }
    __syncthreads();

    unsigned qa[8][4];
    #pragma unroll
    for (int ks = 0; ks < 8; ks++) {
        int kc = ks * 8 + gc;
        qa[ks][0] = sP[i0 * APAD + kc];
        qa[ks][1] = sP[(i0 + 8) * APAD + kc];
        qa[ks][2] = sP[i0 * APAD + kc + 4];
        qa[ks][3] = sP[(i0 + 8) * APAD + kc + 4];
    }

    float O[8][4] = {};
    float m0r = -1e30f, m1r = -1e30f, l0r = 0.f, l1r = 0.f;

    for (int kt = 0; kt <= qt; kt++) {
        __syncthreads();   // all warps done with sV/sP of previous tile
        #pragma unroll
        for (int i = 0; i < 8; i++) {
            int f4 = i * 128 + tid;
            int r = f4 >> 4, c = (f4 & 15) << 2;
            float4 kv = *(const float4*)&Kg[(size_t)((kt << 6) + r) * HD + c];
            float4 vv = *(const float4*)&Vg[(size_t)((kt << 6) + r) * HD + c];
            sK[r * APAD + c + 0] = f2tf(kv.x);
            sK[r * APAD + c + 1] = f2tf(kv.y);
            sK[r * APAD + c + 2] = f2tf(kv.z);
            sK[r * APAD + c + 3] = f2tf(kv.w);
            sV[r * APAD + c + 0] = f2tf(vv.x);
            sV[r * APAD + c + 1] = f2tf(vv.y);
            sV[r * APAD + c + 2] = f2tf(vv.z);
            sV[r * APAD + c + 3] = f2tf(vv.w);
        }
        __syncthreads();

        // ---- S = Qs @ K^T ----
        float S[8][4] = {};
        #pragma unroll
        for (int ks = 0; ks < 8; ks++) {
            int kc = ks * 8 + gc;   // dim index
            #pragma unroll
            for (int nt = 0; nt < 8; nt++) {
                int n = nt * 8 + gi;   // key index
                unsigned b0 = sK[n * APAD + kc];
                unsigned b1 = sK[n * APAD + kc + 4];
                mma8(S[nt], qa[ks][0], qa[ks][1], qa[ks][2], qa[ks][3], b0, b1);
            }
        }

        // ---- causal mask (diagonal tile only) ----
        if (kt == qt) {
            #pragma unroll
            for (int nt = 0; nt < 8; nt++) {
                int j0 = nt * 8 + 2 * gc;
                if (j0 > i0)          S[nt][0] = -1e30f;
                if (j0 + 1 > i0)      S[nt][1] = -1e30f;
                if (j0 > i0 + 8)      S[nt][2] = -1e30f;
                if (j0 + 1 > i0 + 8)  S[nt][3] = -1e30f;
            }
        }

        // ---- online softmax ----
        float mx0 = -1e30f, mx1 = -1e30f;
        #pragma unroll
        for (int nt = 0; nt < 8; nt++) {
            mx0 = fmaxf(mx0, fmaxf(S[nt][0], S[nt][1]));
            mx1 = fmaxf(mx1, fmaxf(S[nt][2], S[nt][3]));
        }
        mx0 = fmaxf(mx0, __shfl_xor_sync(0xffffffffu, mx0, 1));
        mx0 = fmaxf(mx0, __shfl_xor_sync(0xffffffffu, mx0, 2));
        mx1 = fmaxf(mx1, __shfl_xor_sync(0xffffffffu, mx1, 1));
        mx1 = fmaxf(mx1, __shfl_xor_sync(0xffffffffu, mx1, 2));

        float mn0 = fmaxf(m0r, mx0);
        float mn1 = fmaxf(m1r, mx1);
        float c0 = __expf(m0r - mn0);
        float c1 = __expf(m1r - mn1);

        float ls0 = 0.f, ls1 = 0.f;
        #pragma unroll
        for (int nt = 0; nt < 8; nt++) {
            int j0 = nt * 8 + 2 * gc;
            float p0 = __expf(S[nt][0] - mn0);
            float p1 = __expf(S[nt][1] - mn0);
            float p2 = __expf(S[nt][2] - mn1);
            float p3 = __expf(S[nt][3] - mn1);
            ls0 += p0 + p1;
            ls1 += p2 + p3;
            sP[i0 * APAD + j0]           = f2tf(p0);
            sP[i0 * APAD + j0 + 1]       = f2tf(p1);
            sP[(i0 + 8) * APAD + j0]     = f2tf(p2);
            sP[(i0 + 8) * APAD + j0 + 1] = f2tf(p3);
        }
        ls0 += __shfl_xor_sync(0xffffffffu, ls0, 1);
        ls0 += __shfl_xor_sync(0xffffffffu, ls0, 2);
        ls1 += __shfl_xor_sync(0xffffffffu, ls1, 1);
        ls1 += __shfl_xor_sync(0xffffffffu, ls1, 2);
        l0r = l0r * c0 + ls0;
        l1r = l1r * c1 + ls1;
        m0r = mn0; m1r = mn1;

        #pragma unroll
        for (int nt = 0; nt < 8; nt++) {
            O[nt][0] *= c0; O[nt][1] *= c0;
            O[nt][2] *= c1; O[nt][3] *= c1;
        }

        __syncwarp();  // sP rows produced & consumed within this warp

        // ---- O += P @ V ----
        #pragma unroll
        for (int ks = 0; ks < 8; ks++) {
            int kb = ks * 8 + gc;   // key index
            unsigned a0 = sP[i0 * APAD + kb];
            unsigned a1 = sP[(i0 + 8) * APAD + kb];
            unsigned a2 = sP[i0 * APAD + kb + 4];
            unsigned a3 = sP[(i0 + 8) * APAD + kb + 4];
            #pragma unroll
            for (int nt = 0; nt < 8; nt++) {
                int n = nt * 8 + gi;   // dim index
                unsigned b0 = sV[kb * APAD + n];
                unsigned b1 = sV[(kb + 4) * APAD + n];
                mma8(O[nt], a0, a1, a2, a3, b0, b1);
            }
        }
        __syncwarp();  // sP reads done before next tile's writes
    }

    float inv0 = 1.f / l0r, inv1 = 1.f / l1r;
    float* Og = g_att + (size_t)bh * TT * HD + (size_t)qt * 64 * HD;
    #pragma unroll
    for (int nt = 0; nt < 8; nt++) {
        int j0 = nt * 8 + 2 * gc;
        Og[(i0 << 6) + j0]           = O[nt][0] * inv0;
        Og[(i0 << 6) + j0 + 1]       = O[nt][1] * inv0;
        Og[((i0 + 8) << 6) + j0]     = O[nt][2] * inv1;
        Og[((i0 + 8) << 6) + j0 + 1] = O[nt][3] * inv1;
    }
}

// ---------------------------------------------------------------------------
// Kernel 3: proj GEMM (tf32 mma). A gathered from g_att (B,H,T,hd),
// @ Wproj(1024,1024) + bproj -> out.
// ---------------------------------------------------------------------------
__global__ __launch_bounds__(256) void proj_mma_kernel(
    const float* __restrict__ W, const float* __restrict__ bias,
    float* __restrict__ out)
{
    __shared__ unsigned As[128][36];
    __shared__ unsigned Bs[32][132];

    const int tid  = threadIdx.x;
    const int lane = tid & 31;
    const int warp = tid >> 5;
    const int wm = (warp >> 2) * 64;
    const int wn = (warp & 3) * 32;
    const int m0 = blockIdx.y * 128, n0 = blockIdx.x * 128;

    const int ar = tid >> 3;
    const int ac = (tid & 7) * 4;
    const int bkr = tid >> 5;
    const int bc  = (tid & 31) * 4;

    float C[4][4][4] = {};

    for (int k0 = 0; k0 < CC; k0 += 32) {
        float4 av[4], bv[4];
        #pragma unroll
        for (int i = 0; i < 4; i++) {
            int m = m0 + ar + 32 * i;
            int b = m >> 11, t = m & 2047;
            int k = k0 + ac;
            int h = k >> 6, d = k & 63;
            av[i] = *(const float4*)&g_att[((size_t)(((b << 4) + h) << 11) + t) * HD + d];
        }
        #pragma unroll
        for (int i = 0; i < 4; i++)
            bv[i] = *(const float4*)&W[(size_t)(k0 + bkr + 8 * i) * CC + n0 + bc];

        __syncthreads();
        #pragma unroll
        for (int i = 0; i < 4; i++) {
            As[ar + 32 * i][ac + 0] = f2tf(av[i].x);
            As[ar + 32 * i][ac + 1] = f2tf(av[i].y);
            As[ar + 32 * i][ac + 2] = f2tf(av[i].z);
            As[ar + 32 * i][ac + 3] = f2tf(av[i].w);
            Bs[bkr + 8 * i][bc + 0] = f2tf(bv[i].x);
            Bs[bkr + 8 * i][bc + 1] = f2tf(bv[i].y);
            Bs[bkr + 8 * i][bc + 2] = f2tf(bv[i].z);
            Bs[bkr + 8 * i][bc + 3] = f2tf(bv[i].w);
        }
        __syncthreads();

        #pragma unroll
        for (int ks = 0; ks < 4; ks++) {
            const int kc = ks * 8 + (lane & 3);
            unsigned a[4][4], b[4][2];
            #pragma unroll
            for (int tm = 0; tm < 4; tm++) {
                int r = wm + tm * 16 + (lane >> 2);
                a[tm][0] = As[r][kc];
                a[tm][1] = As[r + 8][kc];
                a[tm][2] = As[r][kc + 4];
                a[tm][3] = As[r + 8][kc + 4];
            }
            #pragma unroll
            for (int tn = 0; tn < 4; tn++) {
                int n = wn + tn * 8 + (lane >> 2);
                b[tn][0] = Bs[kc][n];
                b[tn][1] = Bs[kc + 4][n];
            }
            #pragma unroll
            for (int tm = 0; tm < 4; tm++)
                #pragma unroll
                for (int tn = 0; tn < 4; tn++)
                    mma8(C[tm][tn], a[tm][0], a[tm][1], a[tm][2], a[tm][3],
                         b[tn][0], b[tn][1]);
        }
    }

    #pragma unroll
    for (int tm = 0; tm < 4; tm++) {
        #pragma unroll
        for (int tn = 0; tn < 4; tn++) {
            #pragma unroll
            for (int e = 0; e < 4; e++) {
                int m = m0 + wm + tm * 16 + (lane >> 2) + ((e >= 2) ? 8 : 0);
                int n = n0 + wn + tn * 8 + 2 * (lane & 3) + (e & 1);
                out[(size_t)m * CC + n] = C[tm][tn][e] + bias[n];
            }
        }
    }
}

// ---------------------------------------------------------------------------
extern "C" void kernel_launch(void* const* d_in, const int* in_sizes, int n_in,
                              void* d_out, int out_size)
{
    const float* x     = (const float*)d_in[0];
    const float* Wqkv  = (const float*)d_in[1];
    const float* bqkv  = (const float*)d_in[2];
    const float* Wproj = (const float*)d_in[3];
    const float* bproj = (const float*)d_in[4];
    float* out = (float*)d_out;

    const size_t ATTN_SMEM = (size_t)3 * 64 * APAD * sizeof(unsigned);  // 52224 B
    cudaFuncSetAttribute(attn_mma_kernel,
                         cudaFuncAttributeMaxDynamicSharedMemorySize,
                         (int)ATTN_SMEM);

    qkv_mma_kernel<<<dim3(24, 32), 256>>>(x, Wqkv, bqkv);           // 3072/128 x 4096/128
    attn_mma_kernel<<<dim3(32, 32), 128, ATTN_SMEM>>>();            // qtiles x BH
    proj_mma_kernel<<<dim3(8, 32), 256>>>(Wproj, bproj, out);       // 1024/128 x 4096/128
}

// round 3
// speedup vs baseline: 5.4869x; 1.1102x over previous
#include <cuda_runtime.h>
#include <math.h>

#define BB 2
#define TT 2048
#define CC 1024
#define NH 16
#define HD 64
#define BH (BB*NH)

// scratch (tf32-encoded floats unless noted)
__device__ float g_q[(size_t)BH * TT * HD];      // pre-scaled by 1/8, tf32
__device__ float g_k[(size_t)BH * TT * HD];      // tf32
__device__ float g_v[(size_t)BH * TT * HD];      // tf32
__device__ float g_att[(size_t)BH * TT * HD];    // tf32
__device__ float g_xt[(size_t)BB * TT * CC];     // tf32 copy of x
__device__ float g_wqkv[(size_t)CC * 3 * CC];    // tf32 copy of Wqkv
__device__ float g_wproj[(size_t)CC * CC];       // tf32 copy of Wproj

// ---------------------------------------------------------------------------
__device__ __forceinline__ unsigned f2tf(float f) {
    unsigned u;
    asm("cvt.rna.tf32.f32 %0, %1;" : "=r"(u) : "f"(f));
    return u;
}

__device__ __forceinline__ void mma8(float* c,
                                     unsigned a0, unsigned a1, unsigned a2, unsigned a3,
                                     unsigned b0, unsigned b1) {
    asm volatile(
        "mma.sync.aligned.m16n8k8.row.col.f32.tf32.tf32.f32 "
        "{%0,%1,%2,%3}, {%4,%5,%6,%7}, {%8,%9}, {%0,%1,%2,%3};"
        : "+f"(c[0]), "+f"(c[1]), "+f"(c[2]), "+f"(c[3])
        : "r"(a0), "r"(a1), "r"(a2), "r"(a3), "r"(b0), "r"(b1));
}

__device__ __forceinline__ void cpa16(float* smem_dst, const float* gptr) {
    unsigned s = (unsigned)__cvta_generic_to_shared(smem_dst);
    asm volatile("cp.async.cg.shared.global [%0], [%1], 16;" :: "r"(s), "l"(gptr));
}
#define CP_COMMIT asm volatile("cp.async.commit_group;")
#define CP_WAIT1  asm volatile("cp.async.wait_group 1;")
#define CP_WAIT0  asm volatile("cp.async.wait_group 0;")

// ---------------------------------------------------------------------------
// tf32 pre-convert pass (float4 elementwise)
// ---------------------------------------------------------------------------
__global__ __launch_bounds__(256) void cvt_kernel(const float* __restrict__ in,
                                                  float* __restrict__ out)
{
    size_t i = ((size_t)blockIdx.x * 256 + threadIdx.x) * 4;
    float4 v = *(const float4*)&in[i];
    v.x = __uint_as_float(f2tf(v.x));
    v.y = __uint_as_float(f2tf(v.y));
    v.z = __uint_as_float(f2tf(v.z));
    v.w = __uint_as_float(f2tf(v.w));
    *(float4*)&out[i] = v;
}

// ---------------------------------------------------------------------------
// Kernel 1: QKV GEMM, tf32 mma, cp.async 2-stage pipeline.
// A = g_xt (4096,1024), B = g_wqkv (1024,3072), block tile 128x128, BK=32.
// ---------------------------------------------------------------------------
#define AS_STRIDE 36
#define BS_STRIDE 132
#define AS_SZ (128*AS_STRIDE)
#define BS_SZ (32*BS_STRIDE)

__global__ __launch_bounds__(256) void qkv_mma_kernel(const float* __restrict__ bias)
{
    extern __shared__ float smem[];
    float* As = smem;              // [2][128][36]
    float* Bs = smem + 2 * AS_SZ;  // [2][32][132]

    const int tid  = threadIdx.x;
    const int lane = tid & 31;
    const int warp = tid >> 5;
    const int wm = (warp >> 2) * 64;
    const int wn = (warp & 3) * 32;
    const int m0 = blockIdx.y * 128, n0 = blockIdx.x * 128;

    const int ar = tid >> 3, ac = (tid & 7) * 4;
    const int bkr = tid >> 5, bc = (tid & 31) * 4;

    float C[4][4][4] = {};

#define QKV_LOAD(s, k0)                                                          \
    {                                                                            \
        _Pragma("unroll")                                                        \
        for (int i = 0; i < 4; i++) {                                            \
            cpa16(&As[(s)*AS_SZ + (ar + 32*i)*AS_STRIDE + ac],                   \
                  &g_xt[(size_t)(m0 + ar + 32*i) * CC + (k0) + ac]);             \
            cpa16(&Bs[(s)*BS_SZ + (bkr + 8*i)*BS_STRIDE + bc],                   \
                  &g_wqkv[(size_t)((k0) + bkr + 8*i) * (3*CC) + n0 + bc]);       \
        }                                                                        \
        CP_COMMIT;                                                               \
    }

    QKV_LOAD(0, 0);

    for (int it = 0; it < 32; it++) {
        const int s = it & 1;
        if (it + 1 < 32) { QKV_LOAD(s ^ 1, (it + 1) * 32); CP_WAIT1; }
        else             { CP_WAIT0; }
        __syncthreads();

        const float* Asb = As + s * AS_SZ;
        const float* Bsb = Bs + s * BS_SZ;
        #pragma unroll
        for (int ks = 0; ks < 4; ks++) {
            const int kc = ks * 8 + (lane & 3);
            unsigned a[4][4], b[4][2];
            #pragma unroll
            for (int tm = 0; tm < 4; tm++) {
                int r = wm + tm * 16 + (lane >> 2);
                a[tm][0] = __float_as_uint(Asb[r * AS_STRIDE + kc]);
                a[tm][1] = __float_as_uint(Asb[(r + 8) * AS_STRIDE + kc]);
                a[tm][2] = __float_as_uint(Asb[r * AS_STRIDE + kc + 4]);
                a[tm][3] = __float_as_uint(Asb[(r + 8) * AS_STRIDE + kc + 4]);
            }
            #pragma unroll
            for (int tn = 0; tn < 4; tn++) {
                int n = wn + tn * 8 + (lane >> 2);
                b[tn][0] = __float_as_uint(Bsb[kc * BS_STRIDE + n]);
                b[tn][1] = __float_as_uint(Bsb[(kc + 4) * BS_STRIDE + n]);
            }
            #pragma unroll
            for (int tm = 0; tm < 4; tm++)
                #pragma unroll
                for (int tn = 0; tn < 4; tn++)
                    mma8(C[tm][tn], a[tm][0], a[tm][1], a[tm][2], a[tm][3],
                         b[tn][0], b[tn][1]);
        }
        __syncthreads();
    }

    // epilogue: bias, tf32-round, scatter to (B,H,T,hd); q pre-scaled by 1/8
    #pragma unroll
    for (int tm = 0; tm < 4; tm++) {
        #pragma unroll
        for (int tn = 0; tn < 4; tn++) {
            #pragma unroll
            for (int e = 0; e < 4; e++) {
                int m = m0 + wm + tm * 16 + (lane >> 2) + ((e >= 2) ? 8 : 0);
                int n = n0 + wn + tn * 8 + 2 * (lane & 3) + (e & 1);
                float v = C[tm][tn][e] + bias[n];
                int b = m >> 11, t = m & 2047;
                int h = n / 192;
                int r = n - h * 192;
                int d = r & 63;
                float ov;
                float* dst;
                if (r < 64)       { dst = g_q; ov = __uint_as_float(f2tf(v * 0.125f)); }
                else if (r < 128) { dst = g_k; ov = __uint_as_float(f2tf(v)); }
                else              { dst = g_v; ov = __uint_as_float(f2tf(v)); }
                dst[((size_t)(((b << 4) + h) << 11) + t) * HD + d] = ov;
            }
        }
    }
}

// ---------------------------------------------------------------------------
// Kernel 2: causal flash attention. 256 threads (8 warps), 128-query tile,
// 64-key tiles, cp.async double-buffered K/V, tf32 mma throughout.
// Warp w owns query rows w*16..w*16+15 (fragment rows i0, i0+8).
// ---------------------------------------------------------------------------
#define APAD 68
#define KV_SZ (64*APAD)

__global__ __launch_bounds__(256) void attn_mma_kernel()
{
    extern __shared__ float sm[];
    float* sK = sm;                 // [2][64][68]
    float* sV = sm + 2 * KV_SZ;     // [2][64][68]
    float* sP = sm + 4 * KV_SZ;     // [128][68] (Q staging, then P)

    const int qt = blockIdx.x;
    const int bh = blockIdx.y;
    const int tid = threadIdx.x;
    const int lane = tid & 31;
    const int warp = tid >> 5;
    const int gi = lane >> 2;
    const int gc = lane & 3;
    const int i0 = warp * 16 + gi;

    const float* Qg = g_q + (size_t)bh * TT * HD + (size_t)qt * 128 * HD;
    const float* Kg = g_k + (size_t)bh * TT * HD;
    const float* Vg = g_v + (size_t)bh * TT * HD;

    // stage Q (already scaled+tf32) into sP
    #pragma unroll
    for (int i = 0; i < 8; i++) {
        int f4 = i * 256 + tid;            // 2048 float4
        int r = f4 >> 4, c = (f4 & 15) << 2;
        cpa16(&sP[r * APAD + c], &Qg[(r << 6) + c]);
    }
    CP_COMMIT;

#define KV_LOAD(s, kt)                                                       \
    {                                                                        \
        _Pragma("unroll")                                                    \
        for (int i = 0; i < 4; i++) {                                        \
            int f4 = i * 256 + tid;                                          \
            int r = f4 >> 4, c = (f4 & 15) << 2;                             \
            cpa16(&sK[((s)*64 + r) * APAD + c],                              \
                  &Kg[(size_t)(((kt) << 6) + r) * HD + c]);                  \
            cpa16(&sV[((s)*64 + r) * APAD + c],                              \
                  &Vg[(size_t)(((kt) << 6) + r) * HD + c]);                  \
        }                                                                    \
        CP_COMMIT;                                                           \
    }

    const int ktmax = 2 * qt + 1;
    KV_LOAD(0, 0);

    unsigned qa[8][4];
    float O[8][4] = {};
    float m0r = -1e30f, m1r = -1e30f, l0r = 0.f, l1r = 0.f;

    for (int kt = 0; kt <= ktmax; kt++) {
        const int s = kt & 1;
        if (kt < ktmax) { KV_LOAD(s ^ 1, kt + 1); CP_WAIT1; }
        else            { CP_WAIT0; }
        __syncthreads();

        if (kt == 0) {
            #pragma unroll
            for (int ks = 0; ks < 8; ks++) {
                int kc = ks * 8 + gc;
                qa[ks][0] = __float_as_uint(sP[i0 * APAD + kc]);
                qa[ks][1] = __float_as_uint(sP[(i0 + 8) * APAD + kc]);
                qa[ks][2] = __float_as_uint(sP[i0 * APAD + kc + 4]);
                qa[ks][3] = __float_as_uint(sP[(i0 + 8) * APAD + kc + 4]);
            }
        }

        // warp-uniform skip: all this warp's rows above every key in tile
        const bool active = (kt * 64 <= qt * 128 + warp * 16 + 15);
        if (active) {
            const float* sKb = sK + s * KV_SZ;
            const float* sVb = sV + s * KV_SZ;

            float S[8][4] = {};
            #pragma unroll
            for (int ks = 0; ks < 8; ks++) {
                int kc = ks * 8 + gc;
                #pragma unroll
                for (int nt = 0; nt < 8; nt++) {
                    int n = nt * 8 + gi;
                    unsigned b0 = __float_as_uint(sKb[n * APAD + kc]);
                    unsigned b1 = __float_as_uint(sKb[n * APAD + kc + 4]);
                    mma8(S[nt], qa[ks][0], qa[ks][1], qa[ks][2], qa[ks][3], b0, b1);
                }
            }

            if (kt >= 2 * qt) {  // diagonal region: per-element causal mask
                int ig0 = qt * 128 + i0;
                #pragma unroll
                for (int nt = 0; nt < 8; nt++) {
                    int j0 = kt * 64 + nt * 8 + 2 * gc;
                    if (j0 > ig0)         S[nt][0] = -1e30f;
                    if (j0 + 1 > ig0)     S[nt][1] = -1e30f;
                    if (j0 > ig0 + 8)     S[nt][2] = -1e30f;
                    if (j0 + 1 > ig0 + 8) S[nt][3] = -1e30f;
                }
            }

            float mx0 = -1e30f, mx1 = -1e30f;
            #pragma unroll
            for (int nt = 0; nt < 8; nt++) {
                mx0 = fmaxf(mx0, fmaxf(S[nt][0], S[nt][1]));
                mx1 = fmaxf(mx1, fmaxf(S[nt][2], S[nt][3]));
            }
            mx0 = fmaxf(mx0, __shfl_xor_sync(0xffffffffu, mx0, 1));
            mx0 = fmaxf(mx0, __shfl_xor_sync(0xffffffffu, mx0, 2));
            mx1 = fmaxf(mx1, __shfl_xor_sync(0xffffffffu, mx1, 1));
            mx1 = fmaxf(mx1, __shfl_xor_sync(0xffffffffu, mx1, 2));

            float mn0 = fmaxf(m0r, mx0), mn1 = fmaxf(m1r, mx1);
            float c0 = __expf(m0r - mn0), c1 = __expf(m1r - mn1);

            float ls0 = 0.f, ls1 = 0.f;
            #pragma unroll
            for (int nt = 0; nt < 8; nt++) {
                int j0 = nt * 8 + 2 * gc;
                float p0 = __expf(S[nt][0] - mn0);
                float p1 = __expf(S[nt][1] - mn0);
                float p2 = __expf(S[nt][2] - mn1);
                float p3 = __expf(S[nt][3] - mn1);
                ls0 += p0 + p1;
                ls1 += p2 + p3;
                sP[i0 * APAD + j0]           = __uint_as_float(f2tf(p0));
                sP[i0 * APAD + j0 + 1]       = __uint_as_float(f2tf(p1));
                sP[(i0 + 8) * APAD + j0]     = __uint_as_float(f2tf(p2));
                sP[(i0 + 8) * APAD + j0 + 1] = __uint_as_float(f2tf(p3));
            }
            ls0 += __shfl_xor_sync(0xffffffffu, ls0, 1);
            ls0 += __shfl_xor_sync(0xffffffffu, ls0, 2);
            ls1 += __shfl_xor_sync(0xffffffffu, ls1, 1);
            ls1 += __shfl_xor_sync(0xffffffffu, ls1, 2);
            l0r = l0r * c0 + ls0;
            l1r = l1r * c1 + ls1;
            m0r = mn0; m1r = mn1;

            #pragma unroll
            for (int nt = 0; nt < 8; nt++) {
                O[nt][0] *= c0; O[nt][1] *= c0;
                O[nt][2] *= c1; O[nt][3] *= c1;
            }

            __syncwarp();

            #pragma unroll
            for (int ks = 0; ks < 8; ks++) {
                int kb = ks * 8 + gc;
                unsigned a0 = __float_as_uint(sP[i0 * APAD + kb]);
                unsigned a1 = __float_as_uint(sP[(i0 + 8) * APAD + kb]);
                unsigned a2 = __float_as_uint(sP[i0 * APAD + kb + 4]);
                unsigned a3 = __float_as_uint(sP[(i0 + 8) * APAD + kb + 4]);
                #pragma unroll
                for (int nt = 0; nt < 8; nt++) {
                    int n = nt * 8 + gi;
                    unsigned b0 = __float_as_uint(sVb[kb * APAD + n]);
                    unsigned b1 = __float_as_uint(sVb[(kb + 4) * APAD + n]);
                    mma8(O[nt], a0, a1, a2, a3, b0, b1);
                }
            }
            __syncwarp();
        }
        __syncthreads();
    }

    float inv0 = 1.f / l0r, inv1 = 1.f / l1r;
    float* Og = g_att + (size_t)bh * TT * HD + (size_t)qt * 128 * HD;
    #pragma unroll
    for (int nt = 0; nt < 8; nt++) {
        int j0 = nt * 8 + 2 * gc;
        Og[(i0 << 6) + j0]           = __uint_as_float(f2tf(O[nt][0] * inv0));
        Og[(i0 << 6) + j0 + 1]       = __uint_as_float(f2tf(O[nt][1] * inv0));
        Og[((i0 + 8) << 6) + j0]     = __uint_as_float(f2tf(O[nt][2] * inv1));
        Og[((i0 + 8) << 6) + j0 + 1] = __uint_as_float(f2tf(O[nt][3] * inv1));
    }
}

// ---------------------------------------------------------------------------
// Kernel 3: proj GEMM, A gathered from g_att (tf32), B = g_wproj (tf32),
// cp.async 2-stage pipeline, fp32 out.
// ---------------------------------------------------------------------------
__global__ __launch_bounds__(256) void proj_mma_kernel(const float* __restrict__ bias,
                                                       float* __restrict__ out)
{
    extern __shared__ float smem[];
    float* As = smem;
    float* Bs = smem + 2 * AS_SZ;

    const int tid  = threadIdx.x;
    const int lane = tid & 31;
    const int warp = tid >> 5;
    const int wm = (warp >> 2) * 64;
    const int wn = (warp & 3) * 32;
    const int m0 = blockIdx.y * 128, n0 = blockIdx.x * 128;

    const int ar = tid >> 3, ac = (tid & 7) * 4;
    const int bkr = tid >> 5, bc = (tid & 31) * 4;

    float C[4][4][4] = {};

#define PROJ_LOAD(s, k0)                                                           \
    {                                                                              \
        int h = (k0) >> 6, d = ((k0) & 63) + ac;                                   \
        _Pragma("unroll")                                                          \
        for (int i = 0; i < 4; i++) {                                              \
            int m = m0 + ar + 32 * i;                                              \
            int b = m >> 11, t = m & 2047;                                         \
            cpa16(&As[(s)*AS_SZ + (ar + 32*i)*AS_STRIDE + ac],                     \
                  &g_att[((size_t)(((b << 4) + h) << 11) + t) * HD + d]);          \
            cpa16(&Bs[(s)*BS_SZ + (bkr + 8*i)*BS_STRIDE + bc],                     \
                  &g_wproj[(size_t)((k0) + bkr + 8*i) * CC + n0 + bc]);            \
        }                                                                          \
        CP_COMMIT;                                                                 \
    }

    PROJ_LOAD(0, 0);

    for (int it = 0; it < 32; it++) {
        const int s = it & 1;
        if (it + 1 < 32) { PROJ_LOAD(s ^ 1, (it + 1) * 32); CP_WAIT1; }
        else             { CP_WAIT0; }
        __syncthreads();

        const float* Asb = As + s * AS_SZ;
        const float* Bsb = Bs + s * BS_SZ;
        #pragma unroll
        for (int ks = 0; ks < 4; ks++) {
            const int kc = ks * 8 + (lane & 3);
            unsigned a[4][4], b[4][2];
            #pragma unroll
            for (int tm = 0; tm < 4; tm++) {
                int r = wm + tm * 16 + (lane >> 2);
                a[tm][0] = __float_as_uint(Asb[r * AS_STRIDE + kc]);
                a[tm][1] = __float_as_uint(Asb[(r + 8) * AS_STRIDE + kc]);
                a[tm][2] = __float_as_uint(Asb[r * AS_STRIDE + kc + 4]);
                a[tm][3] = __float_as_uint(Asb[(r + 8) * AS_STRIDE + kc + 4]);
            }
            #pragma unroll
            for (int tn = 0; tn < 4; tn++) {
                int n = wn + tn * 8 + (lane >> 2);
                b[tn][0] = __float_as_uint(Bsb[kc * BS_STRIDE + n]);
                b[tn][1] = __float_as_uint(Bsb[(kc + 4) * BS_STRIDE + n]);
            }
            #pragma unroll
            for (int tm = 0; tm < 4; tm++)
                #pragma unroll
                for (int tn = 0; tn < 4; tn++)
                    mma8(C[tm][tn], a[tm][0], a[tm][1], a[tm][2], a[tm][3],
                         b[tn][0], b[tn][1]);
        }
        __syncthreads();
    }

    #pragma unroll
    for (int tm = 0; tm < 4; tm++) {
        #pragma unroll
        for (int tn = 0; tn < 4; tn++) {
            #pragma unroll
            for (int e = 0; e < 4; e++) {
                int m = m0 + wm + tm * 16 + (lane >> 2) + ((e >= 2) ? 8 : 0);
                int n = n0 + wn + tn * 8 + 2 * (lane & 3) + (e & 1);
                out[(size_t)m * CC + n] = C[tm][tn][e] + bias[n];
            }
        }
    }
}

// ---------------------------------------------------------------------------
extern "C" void kernel_launch(void* const* d_in, const int* in_sizes, int n_in,
                              void* d_out, int out_size)
{
    const float* x     = (const float*)d_in[0];
    const float* Wqkv  = (const float*)d_in[1];
    const float* bqkv  = (const float*)d_in[2];
    const float* Wproj = (const float*)d_in[3];
    const float* bproj = (const float*)d_in[4];
    float* out = (float*)d_out;

    static int attr_done = 0;
    const int GEMM_SMEM = (2 * AS_SZ + 2 * BS_SZ) * 4;              // 70656 B
    const int ATTN_SMEM = (4 * KV_SZ + 128 * APAD) * 4;             // 104448 B
    if (!attr_done) {
        cudaFuncSetAttribute(qkv_mma_kernel,
                             cudaFuncAttributeMaxDynamicSharedMemorySize, GEMM_SMEM);
        cudaFuncSetAttribute(proj_mma_kernel,
                             cudaFuncAttributeMaxDynamicSharedMemorySize, GEMM_SMEM);
        cudaFuncSetAttribute(attn_mma_kernel,
                             cudaFuncAttributeMaxDynamicSharedMemorySize, ATTN_SMEM);
        attr_done = 1;
    }

    float* xt; float* wq; float* wp;
    cudaGetSymbolAddress((void**)&xt, g_xt);
    cudaGetSymbolAddress((void**)&wq, g_wqkv);
    cudaGetSymbolAddress((void**)&wp, g_wproj);

    // tf32 pre-convert (float4 per thread)
    cvt_kernel<<<4096, 256>>>(x, xt);       // 4096*1024
    cvt_kernel<<<3072, 256>>>(Wqkv, wq);    // 1024*3072
    cvt_kernel<<<1024, 256>>>(Wproj, wp);   // 1024*1024

    qkv_mma_kernel<<<dim3(24, 32), 256, GEMM_SMEM>>>(bqkv);
    attn_mma_kernel<<<dim3(16, 32), 256, ATTN_SMEM>>>();
    proj_mma_kernel<<<dim3(8, 32), 256, GEMM_SMEM>>>(bproj, out);
}